// round 16
// baseline (speedup 1.0000x reference)
#include <cuda_runtime.h>
#include <cuda_bf16.h>
#include <cstdint>
#include <stdint.h>
#include <math.h>

// Problem constants
#define BB 64      // batch
#define TT 256     // time
#define DD 512     // input dim
#define HH 1024    // hidden
#define G3 3072    // 3*H
#define G2 2048    // 2*H
#define KSA 4      // K-split for h@Wh^T  (1024/4 = 256 per chunk)
#define KSC 8      // K-split for rh@Wc^T (1024/8 = 128 per chunk)
#define NB 128     // persistent CTAs
#define NTH 256    // threads per CTA

// smem strides (floats)
#define WASTR 260  // Wh chunk / staged-h row stride (256 cols)
#define WCSTR 132  // Wc chunk / staged-rh row stride (128 cols)
#define RSTR  66   // reduction scratch row stride

// ---------------- scratch (device globals; no allocs allowed) ----------------
__device__ float g_ig[(size_t)TT * BB * G3];     // [T][B][3H] precomputed input gates
__device__ float g_p[BB * G3];                   // [B][3H] peephole gates
__device__ float g_hb[2][BB * HH];               // hidden state, parity buffered (tf32-rounded)
__device__ float g_rhb[2][BB * HH];              // resetgate*h, parity buffered (tf32-rounded)
__device__ float g_part1[2][32 * KSA * 64 * 64]; // [par][tileA][ks][m][n] partials h@Wh^T
__device__ float g_part2[2][16 * KSC * 64 * 64]; // [par][tileC][ks][m][n] partials rh@Wc^T
__device__ float g_Wi_t[G3 * DD];                // tf32-rounded Wi
__device__ float g_Wp_t[G3 * HH];                // tf32-rounded Wp

// dependency flags (monotonic counters, one 128B line each)
__device__ unsigned g_flagA[32 * 32];   // per tileA, 4 producers/step
__device__ unsigned g_flagB[8 * 32];    // per 128-col group, 16 producers/step
__device__ unsigned g_flagC[16 * 32];   // per tileC, 8 producers/step
__device__ unsigned g_flagD[4 * 32];    // per 256-col group, 32 producers/step

// ---------------- tf32 / mma helpers ----------------
__device__ __forceinline__ unsigned f2tf32(float f) {
    unsigned u;
    asm("cvt.rna.tf32.f32 %0, %1;" : "=r"(u) : "f"(f));
    return u;
}
__device__ __forceinline__ float rndf(float f) { return __uint_as_float(f2tf32(f)); }

__device__ __forceinline__ void mma_tf32(float c[4],
                                         unsigned a0, unsigned a1, unsigned a2, unsigned a3,
                                         unsigned b0, unsigned b1)
{
    asm volatile("mma.sync.aligned.m16n8k8.row.col.f32.tf32.tf32.f32 "
                 "{%0,%1,%2,%3},{%4,%5,%6,%7},{%8,%9},{%0,%1,%2,%3};"
                 : "+f"(c[0]), "+f"(c[1]), "+f"(c[2]), "+f"(c[3])
                 : "r"(a0), "r"(a1), "r"(a2), "r"(a3), "r"(b0), "r"(b1));
}

__device__ __forceinline__ void cp16(float* sdst, const float* gsrc) {
    unsigned sa = (unsigned)__cvta_generic_to_shared(sdst);
    asm volatile("cp.async.cg.shared.global [%0], [%1], 16;\n" :: "r"(sa), "l"(gsrc));
}
#define CPA_COMMIT asm volatile("cp.async.commit_group;\n")
#define CPA_WAIT0  asm volatile("cp.async.wait_group 0;\n")
#define PF_L2(a)   asm volatile("prefetch.global.L2 [%0];" :: "l"(a))

// ---- flag primitives ----
// tid0-only acquire spin (low L2 poll pressure), syncthreads wake.
__device__ __forceinline__ void wait_flag(const unsigned* p, unsigned target, int tid) {
    if (tid == 0) {
        unsigned v;
        do {
            asm volatile("ld.acquire.gpu.b32 %0, [%1];" : "=r"(v) : "l"(p) : "memory");
        } while (v < target);
    }
    __syncthreads();
}
// bar.sync orders all CTA threads' prior stores before tid0's release-add
__device__ __forceinline__ void signal_flag(unsigned* p, int tid) {
    __syncthreads();
    if (tid == 0)
        asm volatile("red.add.release.gpu.u32 [%0], 1;" :: "l"(p) : "memory");
}

__device__ __forceinline__ float sigmoidf_(float x) { return 1.0f / (1.0f + expf(-x)); }

// ---------------- weight rounding prologue (Wi, Wp) ----------------
__global__ void round_tf32_kernel(const float* __restrict__ src, float* __restrict__ dst, int n)
{
    int i = blockIdx.x * 256 + threadIdx.x;
    if (i < n) dst[i] = rndf(src[i]);
}

// ---------------- software grid barrier (init only) ----------------
__device__ unsigned g_barcnt = 0;
__device__ volatile unsigned g_bargen = 0;

__device__ __forceinline__ void grid_sync() {
    __syncthreads();
    if (threadIdx.x == 0) {
        __threadfence();
        unsigned g0 = g_bargen;
        unsigned arrived = atomicAdd(&g_barcnt, 1);
        if (arrived == NB - 1) {
            g_barcnt = 0;
            __threadfence();
            g_bargen = g0 + 1;
        } else {
            while (g_bargen == g0) { }
        }
        __threadfence();
    }
    __syncthreads();
}

// ---------------- standalone mma GEMM with bias (ig, p) ----------------
__global__ void __launch_bounds__(NTH)
mma_gemm_bias(const float* __restrict__ A, const float* __restrict__ Wt,
              const float* __restrict__ bias, float* __restrict__ C,
              int K, int N, int xmap)
{
    __shared__ float As[64][36];
    __shared__ float Ws[64][36];
    int tid = threadIdx.x;
    int wid = tid >> 5, lane = tid & 31;
    int wr = wid & 3, wc = wid >> 2;
    int grp = lane >> 2, qd = lane & 3;
    int m0 = blockIdx.y * 64;
    int n0 = blockIdx.x * 64;

    size_t arow[2];
    {
        int r = tid >> 3;
        #pragma unroll
        for (int hh = 0; hh < 2; hh++) {
            int m = m0 + r + 32 * hh;
            if (xmap) { int t = m >> 6, b = m & 63; arow[hh] = ((size_t)b * TT + t) * (size_t)K; }
            else      { arow[hh] = (size_t)m * K; }
        }
    }

    float acc[4][4] = {};
    int c = (tid & 7) * 4;

    for (int k0 = 0; k0 < K; k0 += 32) {
        #pragma unroll
        for (int hh = 0; hh < 2; hh++) {
            float4 v = *reinterpret_cast<const float4*>(A + arow[hh] + k0 + c);
            v.x = rndf(v.x); v.y = rndf(v.y); v.z = rndf(v.z); v.w = rndf(v.w);
            *reinterpret_cast<float4*>(&As[(tid >> 3) + 32 * hh][c]) = v;
        }
        {
            int r = tid >> 3;
            #pragma unroll
            for (int hh = 0; hh < 2; hh++) {
                float4 v = *reinterpret_cast<const float4*>(Wt + (size_t)(n0 + r + 32*hh) * K + k0 + c);
                *reinterpret_cast<float4*>(&Ws[r + 32*hh][c]) = v;
            }
        }
        __syncthreads();
        #pragma unroll
        for (int k8 = 0; k8 < 4; k8++) {
            int kb = k8 * 8;
            unsigned a0 = __float_as_uint(As[16*wr + grp    ][kb + qd    ]);
            unsigned a1 = __float_as_uint(As[16*wr + grp + 8][kb + qd    ]);
            unsigned a2 = __float_as_uint(As[16*wr + grp    ][kb + qd + 4]);
            unsigned a3 = __float_as_uint(As[16*wr + grp + 8][kb + qd + 4]);
            #pragma unroll
            for (int j = 0; j < 4; j++) {
                int nl = 32*wc + 8*j + grp;
                unsigned b0 = __float_as_uint(Ws[nl][kb + qd    ]);
                unsigned b1 = __float_as_uint(Ws[nl][kb + qd + 4]);
                mma_tf32(acc[j], a0, a1, a2, a3, b0, b1);
            }
        }
        __syncthreads();
    }

    #pragma unroll
    for (int half = 0; half < 2; half++) {
        int m = m0 + 16*wr + grp + 8*half;
        #pragma unroll
        for (int j = 0; j < 4; j++) {
            int n = n0 + 32*wc + 8*j + 2*qd;
            float2 v;
            v.x = acc[j][2*half + 0] + bias[n];
            v.y = acc[j][2*half + 1] + bias[n + 1];
            *reinterpret_cast<float2*>(&C[(size_t)m * N + n]) = v;
        }
    }
}

// ---------------- persistent scan kernel (flag-based dataflow) ----------------
__global__ void __launch_bounds__(NTH, 1)
scan_kernel(const float* __restrict__ h0,
            const float* __restrict__ Wh, const float* __restrict__ bh,
            const float* __restrict__ Wc, const float* __restrict__ bc,
            float* __restrict__ out, int want_hT)
{
    extern __shared__ float sm[];
    float* sWA  = sm;                           // [64][WASTR] interleaved Wh tile
    float* sWC  = sWA + 64 * WASTR;             // [64][WCSTR] Wc chunk
    float* sAF  = sWC + 64 * WCSTR;             // [64][WASTR] staged A operand (full chunk)
    float* sRed = sAF + 64 * WASTR;             // [64][RSTR] K-half reduction scratch
    float* sH   = sRed + 64 * RSTR;             // [64][8] own-column h
    float* sGi  = sH + 64 * 8;                  // [64][8] own-column inputgate

    const int job  = blockIdx.x;
    const int tid  = threadIdx.x;
    const int wid  = tid >> 5, lane = tid & 31;
    const int grp  = lane >> 2, qd = lane & 3;

    // warp mapping for GEMM phases: 2-way K-split x (m32 x n32)
    const int kh  = wid >> 2;         // K half 0/1
    const int wr2 = (wid >> 1) & 1;   // m half
    const int wc2 = wid & 1;          // n half
    const int m0w = 32 * wr2, n0w = 32 * wc2;

    // phase A job: interleaved tileA (32 j-cols, both gates) x ksplit
    const int tileA = job >> 2, ksA = job & 3;
    const int j0A = tileA * 32, k0A = ksA * 256;
    // phase C job
    const int tileC = job >> 3, ksC = job & 7;
    const int n0C = tileC * 64, k0C = ksC * 128;
    // owned columns [jc0, jc0+8) for gate epilogues (B and D)
    const int jc0 = 8 * job;
    const int jjA = jc0 - 32 * tileA;   // local col offset in tileA
    const int nnC = jc0 - 64 * tileC;   // local col offset in tileC

    // ---- loop-invariant per-thread values ----
    const int jown = jc0 + (tid & 7);
    const int bown0 = tid >> 3;
    const int bown1 = 32 + (tid >> 3);
    const float bhr = bh[jown];
    const float bhi = bh[HH + jown];
    const float bcj = bc[jown];
    const float pr0 = g_p[(size_t)bown0 * G3 + jown];
    const float pr1 = g_p[(size_t)bown1 * G3 + jown];
    const float pi0 = g_p[(size_t)bown0 * G3 + HH + jown];
    const float pi1 = g_p[(size_t)bown1 * G3 + HH + jown];
    const float pn0 = g_p[(size_t)bown0 * G3 + G2 + jown];
    const float pn1 = g_p[(size_t)bown1 * G3 + G2 + jown];

    // ---- reset flags ----
    if (tid == 0) {
        if (job < 32) g_flagA[job * 32] = 0;
        if (job < 8)  g_flagB[job * 32] = 0;
        if (job < 16) g_flagC[job * 32] = 0;
        if (job < 4)  g_flagD[job * 32] = 0;
    }

    // ---- prologue: persistent weights into smem (tf32-rounded) ----
    #pragma unroll
    for (int i = 0; i < 16; i++) {
        int fi  = tid + i * NTH;
        int row = fi >> 6;
        int c4  = (fi & 63) * 4;
        int wrow = (row < 32) ? (j0A + row) : (HH + j0A + (row - 32));
        float4 v = *reinterpret_cast<const float4*>(Wh + (size_t)wrow * HH + k0A + c4);
        v.x = rndf(v.x); v.y = rndf(v.y); v.z = rndf(v.z); v.w = rndf(v.w);
        *reinterpret_cast<float4*>(sWA + row * WASTR + c4) = v;
    }
    #pragma unroll
    for (int i = 0; i < 8; i++) {
        int fi  = tid + i * NTH;
        int row = fi >> 5;
        int c4  = (fi & 31) * 4;
        float4 v = *reinterpret_cast<const float4*>(Wc + (size_t)(n0C + row) * HH + k0C + c4);
        v.x = rndf(v.x); v.y = rndf(v.y); v.z = rndf(v.z); v.w = rndf(v.w);
        *reinterpret_cast<float4*>(sWC + row * WCSTR + c4) = v;
    }
    // init hbuf[0] = round(h0) and own-column smem h
    {
        int gtid = job * NTH + tid;
        float v0 = rndf(h0[gtid]);
        float v1 = rndf(h0[gtid + NB * NTH]);
        __stcg(&g_hb[0][gtid], v0);
        __stcg(&g_hb[0][gtid + NB * NTH], v1);
        #pragma unroll
        for (int it = 0; it < 2; it++) {
            int e = tid + it * NTH;
            int b = e >> 3, jl = e & 7;
            sH[e] = rndf(h0[b * HH + jc0 + jl]);
        }
    }
    grid_sync();   // once: flags reset + h init visible everywhere

    for (int t = 0; t < TT; t++) {
        const int par = t & 1;
        const float* igt = g_ig + (size_t)t * BB * G3;
        const float* hb_g = g_hb[par];
        float* part1 = g_part1[par] + (size_t)(tileA * KSA + ksA) * 4096;
        float* part2 = g_part2[par] + (size_t)(tileC * KSC + ksC) * 4096;

        // prefetch this step's ig slices into L2
        {
            const float* base0 = igt + (size_t)bown0 * G3 + jown;
            const float* base1 = igt + (size_t)bown1 * G3 + jown;
            PF_L2(base0); PF_L2(base0 + HH); PF_L2(base0 + G2);
            PF_L2(base1); PF_L2(base1 + HH); PF_L2(base1 + G2);
        }

        // ===== Phase A: part1 = h @ WhT(interleaved tile); 2-way warp K-split =====
        wait_flag(&g_flagD[ksA * 32], 32u * t, tid);   // includes syncthreads (sAF safe)
        {
            // stage entire 64x256 h chunk
            #pragma unroll
            for (int i = 0; i < 16; i++) {
                int fi  = tid + i * NTH;
                int row = fi >> 6;
                int c4  = (fi & 63) * 4;
                cp16(sAF + row * WASTR + c4, hb_g + k0A + (size_t)row * HH + c4);
            }
            CPA_COMMIT; CPA_WAIT0;
            __syncthreads();

            float acc[2][4][4] = {};
            const int kbase = kh * 128;
            #pragma unroll
            for (int k8 = 0; k8 < 16; k8++) {
                int kb = kbase + k8 * 8;
                unsigned af[2][4];
                #pragma unroll
                for (int f = 0; f < 2; f++) {
                    int mr = m0w + 16*f + grp;
                    af[f][0] = __float_as_uint(sAF[(mr    ) * WASTR + kb + qd    ]);
                    af[f][1] = __float_as_uint(sAF[(mr + 8) * WASTR + kb + qd    ]);
                    af[f][2] = __float_as_uint(sAF[(mr    ) * WASTR + kb + qd + 4]);
                    af[f][3] = __float_as_uint(sAF[(mr + 8) * WASTR + kb + qd + 4]);
                }
                #pragma unroll
                for (int j = 0; j < 4; j++) {
                    int nl = n0w + 8*j + grp;
                    unsigned b0 = __float_as_uint(sWA[nl * WASTR + kb + qd    ]);
                    unsigned b1 = __float_as_uint(sWA[nl * WASTR + kb + qd + 4]);
                    mma_tf32(acc[0][j], af[0][0], af[0][1], af[0][2], af[0][3], b0, b1);
                    mma_tf32(acc[1][j], af[1][0], af[1][1], af[1][2], af[1][3], b0, b1);
                }
            }
            // K-half reduction: kh=1 warps write scratch, kh=0 add + store
            if (kh == 1) {
                #pragma unroll
                for (int f = 0; f < 2; f++)
                    #pragma unroll
                    for (int j = 0; j < 4; j++)
                        #pragma unroll
                        for (int h = 0; h < 2; h++) {
                            int m = m0w + 16*f + grp + 8*h;
                            int n = n0w + 8*j + 2*qd;
                            float2 v; v.x = acc[f][j][2*h]; v.y = acc[f][j][2*h+1];
                            *reinterpret_cast<float2*>(sRed + m * RSTR + n) = v;
                        }
            }
            __syncthreads();
            if (kh == 0) {
                #pragma unroll
                for (int f = 0; f < 2; f++)
                    #pragma unroll
                    for (int j = 0; j < 4; j++)
                        #pragma unroll
                        for (int h = 0; h < 2; h++) {
                            int m = m0w + 16*f + grp + 8*h;
                            int n = n0w + 8*j + 2*qd;
                            float2 o = *reinterpret_cast<float2*>(sRed + m * RSTR + n);
                            float2 v;
                            v.x = acc[f][j][2*h]   + o.x;
                            v.y = acc[f][j][2*h+1] + o.y;
                            __stcg(reinterpret_cast<float2*>(part1 + m * 64 + n), v);
                        }
            }
        }
        signal_flag(&g_flagA[tileA * 32], tid);

        // ===== Phase B: gates for own 8 columns; needs flagA[tileA] >= 4(t+1) =====
        wait_flag(&g_flagA[tileA * 32], 4u * (t + 1), tid);
        {
            const float* p1 = g_part1[par] + (size_t)tileA * KSA * 4096;
            #pragma unroll
            for (int it = 0; it < 2; it++) {
                int e = tid + it * NTH;
                int b = (it == 0) ? bown0 : bown1;
                int jj = jjA + (tid & 7);
                float hr = bhr, hi = bhi;
                #pragma unroll
                for (int ks = 0; ks < KSA; ks++) {
                    hr += __ldcg(p1 + ks * 4096 + b * 64 + jj);
                    hi += __ldcg(p1 + ks * 4096 + b * 64 + 32 + jj);
                }
                size_t bg = (size_t)b * G3;
                float xr = igt[bg + jown]      + ((it == 0) ? pr0 : pr1);
                float xi = igt[bg + HH + jown] + ((it == 0) ? pi0 : pi1);
                float r  = sigmoidf_(xr + hr);
                float ii = sigmoidf_(xi + hi);
                __stcg(&g_rhb[par][b * HH + jown], rndf(r * sH[e]));
                sGi[e] = ii;
            }
        }
        signal_flag(&g_flagB[(job >> 4) * 32], tid);

        // ===== Phase C: part2 = rh @ WcT; 2-way warp K-split =====
        wait_flag(&g_flagB[ksC * 32], 16u * (t + 1), tid);   // includes syncthreads
        {
            const float* rh_g = g_rhb[par];
            // stage entire 64x128 rh chunk
            #pragma unroll
            for (int i = 0; i < 8; i++) {
                int fi  = tid + i * NTH;
                int row = fi >> 5;
                int c4  = (fi & 31) * 4;
                cp16(sAF + row * WCSTR + c4, rh_g + k0C + (size_t)row * HH + c4);
            }
            CPA_COMMIT; CPA_WAIT0;
            __syncthreads();

            float acc[2][4][4] = {};
            const int kbase = kh * 64;
            #pragma unroll
            for (int k8 = 0; k8 < 8; k8++) {
                int kb = kbase + k8 * 8;
                unsigned af[2][4];
                #pragma unroll
                for (int f = 0; f < 2; f++) {
                    int mr = m0w + 16*f + grp;
                    af[f][0] = __float_as_uint(sAF[(mr    ) * WCSTR + kb + qd    ]);
                    af[f][1] = __float_as_uint(sAF[(mr + 8) * WCSTR + kb + qd    ]);
                    af[f][2] = __float_as_uint(sAF[(mr    ) * WCSTR + kb + qd + 4]);
                    af[f][3] = __float_as_uint(sAF[(mr + 8) * WCSTR + kb + qd + 4]);
                }
                #pragma unroll
                for (int j = 0; j < 4; j++) {
                    int nl = n0w + 8*j + grp;
                    unsigned b0 = __float_as_uint(sWC[nl * WCSTR + kb + qd    ]);
                    unsigned b1 = __float_as_uint(sWC[nl * WCSTR + kb + qd + 4]);
                    mma_tf32(acc[0][j], af[0][0], af[0][1], af[0][2], af[0][3], b0, b1);
                    mma_tf32(acc[1][j], af[1][0], af[1][1], af[1][2], af[1][3], b0, b1);
                }
            }
            if (kh == 1) {
                #pragma unroll
                for (int f = 0; f < 2; f++)
                    #pragma unroll
                    for (int j = 0; j < 4; j++)
                        #pragma unroll
                        for (int h = 0; h < 2; h++) {
                            int m = m0w + 16*f + grp + 8*h;
                            int n = n0w + 8*j + 2*qd;
                            float2 v; v.x = acc[f][j][2*h]; v.y = acc[f][j][2*h+1];
                            *reinterpret_cast<float2*>(sRed + m * RSTR + n) = v;
                        }
            }
            __syncthreads();
            if (kh == 0) {
                #pragma unroll
                for (int f = 0; f < 2; f++)
                    #pragma unroll
                    for (int j = 0; j < 4; j++)
                        #pragma unroll
                        for (int h = 0; h < 2; h++) {
                            int m = m0w + 16*f + grp + 8*h;
                            int n = n0w + 8*j + 2*qd;
                            float2 o = *reinterpret_cast<float2*>(sRed + m * RSTR + n);
                            float2 v;
                            v.x = acc[f][j][2*h]   + o.x;
                            v.y = acc[f][j][2*h+1] + o.y;
                            __stcg(reinterpret_cast<float2*>(part2 + m * 64 + n), v);
                        }
            }
        }
        signal_flag(&g_flagC[tileC * 32], tid);

        // ===== Phase D: newgate+blend for own 8 columns; needs flagC[tileC] >= 8(t+1) =====
        wait_flag(&g_flagC[tileC * 32], 8u * (t + 1), tid);
        float hyv[2];
        {
            const float* p2 = g_part2[par] + (size_t)tileC * KSC * 4096;
            float* hb_n = g_hb[par ^ 1];
            #pragma unroll
            for (int it = 0; it < 2; it++) {
                int e = tid + it * NTH;
                int b = (it == 0) ? bown0 : bown1;
                int nn = nnC + (tid & 7);
                float hn = bcj;
                #pragma unroll
                for (int ks = 0; ks < KSC; ks++)
                    hn += __ldcg(p2 + ks * 4096 + b * 64 + nn);
                size_t bg = (size_t)b * G3;
                float n = tanhf(igt[bg + G2 + jown] + hn + ((it == 0) ? pn0 : pn1));
                float hold = sH[e];
                float hy = hold + sGi[e] * (n - hold);
                float hr_ = rndf(hy);
                sH[e] = hr_;
                __stcg(&hb_n[b * HH + jown], hr_);
                hyv[it] = hy;
            }
        }
        signal_flag(&g_flagD[(job >> 5) * 32], tid);
        // output stores AFTER the release — off the inter-CTA critical path
        #pragma unroll
        for (int it = 0; it < 2; it++) {
            int b = (it == 0) ? bown0 : bown1;
            out[((size_t)b * TT + t) * HH + jown] = hyv[it];
            if (want_hT && t == TT - 1)
                out[(size_t)BB * TT * HH + b * HH + jown] = hyv[it];
        }
    }
}

// ---------------- launch ----------------
extern "C" void kernel_launch(void* const* d_in, const int* in_sizes, int n_in,
                              void* d_out, int out_size)
{
    const float* x   = (const float*)d_in[0];
    const float* h0  = (const float*)d_in[1];
    const float* ctx = (const float*)d_in[2];
    const float* Wi  = (const float*)d_in[3];
    const float* bi  = (const float*)d_in[4];
    const float* Wh  = (const float*)d_in[5];
    const float* bh  = (const float*)d_in[6];
    const float* Wp  = (const float*)d_in[7];
    const float* bp  = (const float*)d_in[8];
    const float* Wc  = (const float*)d_in[9];
    const float* bc  = (const float*)d_in[10];
    float* out = (float*)d_out;

    float *p_ig, *p_p, *p_Wi, *p_Wp;
    cudaGetSymbolAddress((void**)&p_ig, g_ig);
    cudaGetSymbolAddress((void**)&p_p,  g_p);
    cudaGetSymbolAddress((void**)&p_Wi, g_Wi_t);
    cudaGetSymbolAddress((void**)&p_Wp, g_Wp_t);

    static const int SMEM_SCAN =
        (64 * WASTR + 64 * WCSTR + 64 * WASTR + 64 * RSTR + 64 * 8 + 64 * 8) * 4;
    cudaFuncSetAttribute(scan_kernel, cudaFuncAttributeMaxDynamicSharedMemorySize, SMEM_SCAN);

    // prologue: round Wi, Wp to tf32 (Wh, Wc rounded during scan smem load)
    round_tf32_kernel<<<(G3 * DD + 255) / 256, 256>>>(Wi, p_Wi, G3 * DD);
    round_tf32_kernel<<<(G3 * HH + 255) / 256, 256>>>(Wp, p_Wp, G3 * HH);

    // ig_all[t][b][:] = x[b][t][:] @ Wi^T + bi   (time-major)
    mma_gemm_bias<<<dim3(G3 / 64, (TT * BB) / 64), NTH>>>(x, p_Wi, bi, p_ig, DD, G3, 1);

    // p[b][:] = ctx[b] @ Wp^T + bp
    mma_gemm_bias<<<dim3(G3 / 64, 1), NTH>>>(ctx, p_Wp, bp, p_p, HH, G3, 0);

    const int want_hT = (out_size >= (int)((size_t)BB * TT * HH + BB * HH)) ? 1 : 0;

    scan_kernel<<<NB, NTH, SMEM_SCAN>>>(h0, Wh, bh, Wc, bc, out, want_hT);
}

// round 17
// speedup vs baseline: 1.0803x; 1.0803x over previous
#include <cuda_runtime.h>
#include <cuda_bf16.h>
#include <cstdint>
#include <stdint.h>
#include <math.h>

// Problem constants
#define BB 64      // batch
#define TT 256     // time
#define DD 512     // input dim
#define HH 1024    // hidden
#define G3 3072    // 3*H
#define G2 2048    // 2*H
#define KSA 4      // K-split for h@Wh^T  (1024/4 = 256 per chunk)
#define KSC 8      // K-split for rh@Wc^T (1024/8 = 128 per chunk)
#define NB 128     // persistent CTAs
#define NTH 256    // threads per CTA

// smem strides (floats)
#define WASTR 260  // Wh chunk / staged-h row stride (256 cols)
#define WCSTR 132  // Wc chunk / staged-rh row stride (128 cols)

// ---------------- scratch (device globals; no allocs allowed) ----------------
__device__ float g_ig[(size_t)TT * BB * G3];     // [T][B][3H] precomputed input gates
__device__ float g_p[BB * G3];                   // [B][3H] peephole gates
__device__ float g_hb[2][BB * HH];               // hidden state, parity buffered (tf32-rounded)
__device__ float g_rhb[2][BB * HH];              // resetgate*h, parity buffered (tf32-rounded)
__device__ float g_part1[2][32 * KSA * 64 * 64]; // [par][tileA][ks][m][n] partials h@Wh^T
__device__ float g_part2[2][16 * KSC * 64 * 64]; // [par][tileC][ks][m][n] partials rh@Wc^T
__device__ float g_Wi_t[G3 * DD];                // tf32-rounded Wi
__device__ float g_Wp_t[G3 * HH];                // tf32-rounded Wp

// dependency flags (monotonic counters, one 128B line each)
__device__ unsigned g_flagA[32 * 32];   // per tileA, 4 producers/step
__device__ unsigned g_flagB[8 * 32];    // per 128-col group, 16 producers/step
__device__ unsigned g_flagC[16 * 32];   // per tileC, 8 producers/step
__device__ unsigned g_flagD[4 * 32];    // per 256-col group, 32 producers/step

// ---------------- tf32 / mma helpers ----------------
__device__ __forceinline__ unsigned f2tf32(float f) {
    unsigned u;
    asm("cvt.rna.tf32.f32 %0, %1;" : "=r"(u) : "f"(f));
    return u;
}
__device__ __forceinline__ float rndf(float f) { return __uint_as_float(f2tf32(f)); }

__device__ __forceinline__ void mma_tf32(float c[4],
                                         unsigned a0, unsigned a1, unsigned a2, unsigned a3,
                                         unsigned b0, unsigned b1)
{
    asm volatile("mma.sync.aligned.m16n8k8.row.col.f32.tf32.tf32.f32 "
                 "{%0,%1,%2,%3},{%4,%5,%6,%7},{%8,%9},{%0,%1,%2,%3};"
                 : "+f"(c[0]), "+f"(c[1]), "+f"(c[2]), "+f"(c[3])
                 : "r"(a0), "r"(a1), "r"(a2), "r"(a3), "r"(b0), "r"(b1));
}

__device__ __forceinline__ void cp16(float* sdst, const float* gsrc) {
    unsigned sa = (unsigned)__cvta_generic_to_shared(sdst);
    asm volatile("cp.async.cg.shared.global [%0], [%1], 16;\n" :: "r"(sa), "l"(gsrc));
}
#define CPA_COMMIT asm volatile("cp.async.commit_group;\n")
#define CPA_WAIT1  asm volatile("cp.async.wait_group 1;\n")
#define CPA_WAIT0  asm volatile("cp.async.wait_group 0;\n")
#define PF_L2(a)   asm volatile("prefetch.global.L2 [%0];" :: "l"(a))

// ---- flag primitives ----
// all-thread acquire spin (R12-proven), no barrier on wake
__device__ __forceinline__ void wait_flag(const unsigned* p, unsigned target) {
    unsigned v;
    do {
        asm volatile("ld.acquire.gpu.b32 %0, [%1];" : "=r"(v) : "l"(p) : "memory");
    } while (v < target);
}
// bar.sync orders all CTA threads' prior stores before tid0's release-add
__device__ __forceinline__ void signal_flag(unsigned* p, int tid) {
    __syncthreads();
    if (tid == 0)
        asm volatile("red.add.release.gpu.u32 [%0], 1;" :: "l"(p) : "memory");
}

__device__ __forceinline__ float sigmoidf_(float x) { return 1.0f / (1.0f + expf(-x)); }

// ---------------- weight rounding prologue (Wi, Wp) ----------------
__global__ void round_tf32_kernel(const float* __restrict__ src, float* __restrict__ dst, int n)
{
    int i = blockIdx.x * 256 + threadIdx.x;
    if (i < n) dst[i] = rndf(src[i]);
}

// ---------------- software grid barrier (init only) ----------------
__device__ unsigned g_barcnt = 0;
__device__ volatile unsigned g_bargen = 0;

__device__ __forceinline__ void grid_sync() {
    __syncthreads();
    if (threadIdx.x == 0) {
        __threadfence();
        unsigned g0 = g_bargen;
        unsigned arrived = atomicAdd(&g_barcnt, 1);
        if (arrived == NB - 1) {
            g_barcnt = 0;
            __threadfence();
            g_bargen = g0 + 1;
        } else {
            while (g_bargen == g0) { }
        }
        __threadfence();
    }
    __syncthreads();
}

// ---------------- standalone mma GEMM with bias (ig, p) ----------------
__global__ void __launch_bounds__(NTH)
mma_gemm_bias(const float* __restrict__ A, const float* __restrict__ Wt,
              const float* __restrict__ bias, float* __restrict__ C,
              int K, int N, int xmap)
{
    __shared__ float As[64][36];
    __shared__ float Ws[64][36];
    int tid = threadIdx.x;
    int wid = tid >> 5, lane = tid & 31;
    int wr = wid & 3, wc = wid >> 2;
    int grp = lane >> 2, qd = lane & 3;
    int m0 = blockIdx.y * 64;
    int n0 = blockIdx.x * 64;

    size_t arow[2];
    {
        int r = tid >> 3;
        #pragma unroll
        for (int hh = 0; hh < 2; hh++) {
            int m = m0 + r + 32 * hh;
            if (xmap) { int t = m >> 6, b = m & 63; arow[hh] = ((size_t)b * TT + t) * (size_t)K; }
            else      { arow[hh] = (size_t)m * K; }
        }
    }

    float acc[4][4] = {};
    int c = (tid & 7) * 4;

    for (int k0 = 0; k0 < K; k0 += 32) {
        #pragma unroll
        for (int hh = 0; hh < 2; hh++) {
            float4 v = *reinterpret_cast<const float4*>(A + arow[hh] + k0 + c);
            v.x = rndf(v.x); v.y = rndf(v.y); v.z = rndf(v.z); v.w = rndf(v.w);
            *reinterpret_cast<float4*>(&As[(tid >> 3) + 32 * hh][c]) = v;
        }
        {
            int r = tid >> 3;
            #pragma unroll
            for (int hh = 0; hh < 2; hh++) {
                float4 v = *reinterpret_cast<const float4*>(Wt + (size_t)(n0 + r + 32*hh) * K + k0 + c);
                *reinterpret_cast<float4*>(&Ws[r + 32*hh][c]) = v;
            }
        }
        __syncthreads();
        #pragma unroll
        for (int k8 = 0; k8 < 4; k8++) {
            int kb = k8 * 8;
            unsigned a0 = __float_as_uint(As[16*wr + grp    ][kb + qd    ]);
            unsigned a1 = __float_as_uint(As[16*wr + grp + 8][kb + qd    ]);
            unsigned a2 = __float_as_uint(As[16*wr + grp    ][kb + qd + 4]);
            unsigned a3 = __float_as_uint(As[16*wr + grp + 8][kb + qd + 4]);
            #pragma unroll
            for (int j = 0; j < 4; j++) {
                int nl = 32*wc + 8*j + grp;
                unsigned b0 = __float_as_uint(Ws[nl][kb + qd    ]);
                unsigned b1 = __float_as_uint(Ws[nl][kb + qd + 4]);
                mma_tf32(acc[j], a0, a1, a2, a3, b0, b1);
            }
        }
        __syncthreads();
    }

    #pragma unroll
    for (int half = 0; half < 2; half++) {
        int m = m0 + 16*wr + grp + 8*half;
        #pragma unroll
        for (int j = 0; j < 4; j++) {
            int n = n0 + 32*wc + 8*j + 2*qd;
            float2 v;
            v.x = acc[j][2*half + 0] + bias[n];
            v.y = acc[j][2*half + 1] + bias[n + 1];
            *reinterpret_cast<float2*>(&C[(size_t)m * N + n]) = v;
        }
    }
}

// ---------------- persistent scan kernel (flag-based dataflow) ----------------
__global__ void __launch_bounds__(NTH, 1)
scan_kernel(const float* __restrict__ h0,
            const float* __restrict__ Wh, const float* __restrict__ bh,
            const float* __restrict__ Wc, const float* __restrict__ bc,
            float* __restrict__ out, int want_hT)
{
    extern __shared__ float sm[];
    float* sWA = sm;                            // [64][WASTR] interleaved Wh tile
    float* sWC = sWA + 64 * WASTR;              // [64][WCSTR] Wc chunk
    float* sAF = sWC + 64 * WCSTR;              // [64][WASTR] staged A operand (full chunk)
    float* sH  = sAF + 64 * WASTR;              // [64][8] own-column h
    float* sGi = sH + 64 * 8;                   // [64][8] own-column inputgate

    const int job  = blockIdx.x;
    const int tid  = threadIdx.x;
    const int wid  = tid >> 5, lane = tid & 31;
    const int wr   = wid & 3, wc = wid >> 2;
    const int grp  = lane >> 2, qd = lane & 3;
    const int rowA = 16 * wr + grp;

    // phase A job: interleaved tileA (32 j-cols, both gates) x ksplit
    const int tileA = job >> 2, ksA = job & 3;
    const int j0A = tileA * 32, k0A = ksA * 256;
    // phase C job
    const int tileC = job >> 3, ksC = job & 7;
    const int n0C = tileC * 64, k0C = ksC * 128;
    // owned columns [jc0, jc0+8) for gate epilogues (B and D)
    const int jc0 = 8 * job;
    const int jjA = jc0 - 32 * tileA;   // local col offset in tileA
    const int nnC = jc0 - 64 * tileC;   // local col offset in tileC

    // ---- loop-invariant per-thread values ----
    const int jown = jc0 + (tid & 7);
    const int bown0 = tid >> 3;
    const int bown1 = 32 + (tid >> 3);
    const float bhr = bh[jown];
    const float bhi = bh[HH + jown];
    const float bcj = bc[jown];
    const float pr0 = g_p[(size_t)bown0 * G3 + jown];
    const float pr1 = g_p[(size_t)bown1 * G3 + jown];
    const float pi0 = g_p[(size_t)bown0 * G3 + HH + jown];
    const float pi1 = g_p[(size_t)bown1 * G3 + HH + jown];
    const float pn0 = g_p[(size_t)bown0 * G3 + G2 + jown];
    const float pn1 = g_p[(size_t)bown1 * G3 + G2 + jown];

    // ---- reset flags ----
    if (tid == 0) {
        if (job < 32) g_flagA[job * 32] = 0;
        if (job < 8)  g_flagB[job * 32] = 0;
        if (job < 16) g_flagC[job * 32] = 0;
        if (job < 4)  g_flagD[job * 32] = 0;
    }

    // ---- prologue: persistent weights into smem (tf32-rounded) ----
    #pragma unroll
    for (int i = 0; i < 16; i++) {
        int fi  = tid + i * NTH;
        int row = fi >> 6;
        int c4  = (fi & 63) * 4;
        int wrow = (row < 32) ? (j0A + row) : (HH + j0A + (row - 32));
        float4 v = *reinterpret_cast<const float4*>(Wh + (size_t)wrow * HH + k0A + c4);
        v.x = rndf(v.x); v.y = rndf(v.y); v.z = rndf(v.z); v.w = rndf(v.w);
        *reinterpret_cast<float4*>(sWA + row * WASTR + c4) = v;
    }
    #pragma unroll
    for (int i = 0; i < 8; i++) {
        int fi  = tid + i * NTH;
        int row = fi >> 5;
        int c4  = (fi & 31) * 4;
        float4 v = *reinterpret_cast<const float4*>(Wc + (size_t)(n0C + row) * HH + k0C + c4);
        v.x = rndf(v.x); v.y = rndf(v.y); v.z = rndf(v.z); v.w = rndf(v.w);
        *reinterpret_cast<float4*>(sWC + row * WCSTR + c4) = v;
    }
    // init hbuf[0] = round(h0) and own-column smem h
    {
        int gtid = job * NTH + tid;
        float v0 = rndf(h0[gtid]);
        float v1 = rndf(h0[gtid + NB * NTH]);
        __stcg(&g_hb[0][gtid], v0);
        __stcg(&g_hb[0][gtid + NB * NTH], v1);
        #pragma unroll
        for (int it = 0; it < 2; it++) {
            int e = tid + it * NTH;
            int b = e >> 3, jl = e & 7;
            sH[e] = rndf(h0[b * HH + jc0 + jl]);
        }
    }
    grid_sync();   // once: flags reset + h init visible everywhere

    for (int t = 0; t < TT; t++) {
        const int par = t & 1;
        const float* igt = g_ig + (size_t)t * BB * G3;
        const float* hb_g = g_hb[par];
        float* part1 = g_part1[par] + (size_t)(tileA * KSA + ksA) * 4096;
        float* part2 = g_part2[par] + (size_t)(tileC * KSC + ksC) * 4096;

        // prefetch this step's ig slices into L2
        {
            const float* base0 = igt + (size_t)bown0 * G3 + jown;
            const float* base1 = igt + (size_t)bown1 * G3 + jown;
            PF_L2(base0); PF_L2(base0 + HH); PF_L2(base0 + G2);
            PF_L2(base1); PF_L2(base1 + HH); PF_L2(base1 + G2);
        }

        // ===== Phase A: part1 = h @ WhT(interleaved tile); 2-half staged overlap =====
        wait_flag(&g_flagD[ksA * 32], 32u * t);
        __syncthreads();   // protect sAF reuse from previous phase C
        {
            // stage 64x256 h chunk as two K-halves (separate commit groups)
            #pragma unroll
            for (int hf = 0; hf < 2; hf++) {
                #pragma unroll
                for (int i = 0; i < 8; i++) {
                    int fi  = tid + i * NTH;       // 0..2047
                    int row = fi >> 5;             // 0..63
                    int c4  = (fi & 31) * 4 + hf * 128;
                    cp16(sAF + row * WASTR + c4, hb_g + k0A + (size_t)row * HH + c4);
                }
                CPA_COMMIT;
            }

            float acc[4][4] = {};
            CPA_WAIT1;          // first half landed
            __syncthreads();
            #pragma unroll
            for (int s = 0; s < 4; s++) {
                const float* hbp = sAF + s * 32;
                const float* wb  = sWA + s * 32;
                #pragma unroll
                for (int k8 = 0; k8 < 4; k8++) {
                    int kb = k8 * 8;
                    unsigned a0 = __float_as_uint(hbp[(rowA    ) * WASTR + kb + qd    ]);
                    unsigned a1 = __float_as_uint(hbp[(rowA + 8) * WASTR + kb + qd    ]);
                    unsigned a2 = __float_as_uint(hbp[(rowA    ) * WASTR + kb + qd + 4]);
                    unsigned a3 = __float_as_uint(hbp[(rowA + 8) * WASTR + kb + qd + 4]);
                    #pragma unroll
                    for (int j = 0; j < 4; j++) {
                        int nl = 32*wc + 8*j + grp;
                        unsigned b0 = __float_as_uint(wb[nl * WASTR + kb + qd    ]);
                        unsigned b1 = __float_as_uint(wb[nl * WASTR + kb + qd + 4]);
                        mma_tf32(acc[j], a0, a1, a2, a3, b0, b1);
                    }
                }
            }
            CPA_WAIT0;          // second half landed
            __syncthreads();
            #pragma unroll
            for (int s = 4; s < 8; s++) {
                const float* hbp = sAF + s * 32;
                const float* wb  = sWA + s * 32;
                #pragma unroll
                for (int k8 = 0; k8 < 4; k8++) {
                    int kb = k8 * 8;
                    unsigned a0 = __float_as_uint(hbp[(rowA    ) * WASTR + kb + qd    ]);
                    unsigned a1 = __float_as_uint(hbp[(rowA + 8) * WASTR + kb + qd    ]);
                    unsigned a2 = __float_as_uint(hbp[(rowA    ) * WASTR + kb + qd + 4]);
                    unsigned a3 = __float_as_uint(hbp[(rowA + 8) * WASTR + kb + qd + 4]);
                    #pragma unroll
                    for (int j = 0; j < 4; j++) {
                        int nl = 32*wc + 8*j + grp;
                        unsigned b0 = __float_as_uint(wb[nl * WASTR + kb + qd    ]);
                        unsigned b1 = __float_as_uint(wb[nl * WASTR + kb + qd + 4]);
                        mma_tf32(acc[j], a0, a1, a2, a3, b0, b1);
                    }
                }
            }
            #pragma unroll
            for (int half = 0; half < 2; half++) {
                int m = 16*wr + grp + 8*half;
                #pragma unroll
                for (int j = 0; j < 4; j++) {
                    int n = 32*wc + 8*j + 2*qd;
                    float2 v;
                    v.x = acc[j][2*half + 0];
                    v.y = acc[j][2*half + 1];
                    __stcg(reinterpret_cast<float2*>(part1 + m * 64 + n), v);
                }
            }
        }
        signal_flag(&g_flagA[tileA * 32], tid);

        // ===== Phase B: gates for own 8 columns; needs flagA[tileA] >= 4(t+1) =====
        wait_flag(&g_flagA[tileA * 32], 4u * (t + 1));
        {
            const float* p1 = g_part1[par] + (size_t)tileA * KSA * 4096;
            #pragma unroll
            for (int it = 0; it < 2; it++) {
                int e = tid + it * NTH;
                int b = (it == 0) ? bown0 : bown1;
                int jj = jjA + (tid & 7);
                float hr = bhr, hi = bhi;
                #pragma unroll
                for (int ks = 0; ks < KSA; ks++) {
                    hr += __ldcg(p1 + ks * 4096 + b * 64 + jj);
                    hi += __ldcg(p1 + ks * 4096 + b * 64 + 32 + jj);
                }
                size_t bg = (size_t)b * G3;
                float xr = igt[bg + jown]      + ((it == 0) ? pr0 : pr1);
                float xi = igt[bg + HH + jown] + ((it == 0) ? pi0 : pi1);
                float r  = sigmoidf_(xr + hr);
                float ii = sigmoidf_(xi + hi);
                __stcg(&g_rhb[par][b * HH + jown], rndf(r * sH[e]));
                sGi[e] = ii;
            }
        }
        signal_flag(&g_flagB[(job >> 4) * 32], tid);

        // ===== Phase C: part2 = rh @ WcT; 2-half staged overlap =====
        wait_flag(&g_flagB[ksC * 32], 16u * (t + 1));
        __syncthreads();   // protect sAF reuse from phase A
        {
            const float* rh_g = g_rhb[par];
            #pragma unroll
            for (int hf = 0; hf < 2; hf++) {
                #pragma unroll
                for (int i = 0; i < 4; i++) {
                    int fi  = tid + i * NTH;       // 0..1023
                    int row = fi >> 4;             // 0..63
                    int c4  = (fi & 15) * 4 + hf * 64;
                    cp16(sAF + row * WCSTR + c4, rh_g + k0C + (size_t)row * HH + c4);
                }
                CPA_COMMIT;
            }

            float acc[4][4] = {};
            CPA_WAIT1;
            __syncthreads();
            #pragma unroll
            for (int s = 0; s < 2; s++) {
                const float* hbp = sAF + s * 32;
                const float* wb  = sWC + s * 32;
                #pragma unroll
                for (int k8 = 0; k8 < 4; k8++) {
                    int kb = k8 * 8;
                    unsigned a0 = __float_as_uint(hbp[(rowA    ) * WCSTR + kb + qd    ]);
                    unsigned a1 = __float_as_uint(hbp[(rowA + 8) * WCSTR + kb + qd    ]);
                    unsigned a2 = __float_as_uint(hbp[(rowA    ) * WCSTR + kb + qd + 4]);
                    unsigned a3 = __float_as_uint(hbp[(rowA + 8) * WCSTR + kb + qd + 4]);
                    #pragma unroll
                    for (int j = 0; j < 4; j++) {
                        int nl = 32*wc + 8*j + grp;
                        unsigned b0 = __float_as_uint(wb[nl * WCSTR + kb + qd    ]);
                        unsigned b1 = __float_as_uint(wb[nl * WCSTR + kb + qd + 4]);
                        mma_tf32(acc[j], a0, a1, a2, a3, b0, b1);
                    }
                }
            }
            CPA_WAIT0;
            __syncthreads();
            #pragma unroll
            for (int s = 2; s < 4; s++) {
                const float* hbp = sAF + s * 32;
                const float* wb  = sWC + s * 32;
                #pragma unroll
                for (int k8 = 0; k8 < 4; k8++) {
                    int kb = k8 * 8;
                    unsigned a0 = __float_as_uint(hbp[(rowA    ) * WCSTR + kb + qd    ]);
                    unsigned a1 = __float_as_uint(hbp[(rowA + 8) * WCSTR + kb + qd    ]);
                    unsigned a2 = __float_as_uint(hbp[(rowA    ) * WCSTR + kb + qd + 4]);
                    unsigned a3 = __float_as_uint(hbp[(rowA + 8) * WCSTR + kb + qd + 4]);
                    #pragma unroll
                    for (int j = 0; j < 4; j++) {
                        int nl = 32*wc + 8*j + grp;
                        unsigned b0 = __float_as_uint(wb[nl * WCSTR + kb + qd    ]);
                        unsigned b1 = __float_as_uint(wb[nl * WCSTR + kb + qd + 4]);
                        mma_tf32(acc[j], a0, a1, a2, a3, b0, b1);
                    }
                }
            }
            #pragma unroll
            for (int half = 0; half < 2; half++) {
                int m = 16*wr + grp + 8*half;
                #pragma unroll
                for (int j = 0; j < 4; j++) {
                    int n = 32*wc + 8*j + 2*qd;
                    float2 v;
                    v.x = acc[j][2*half + 0];
                    v.y = acc[j][2*half + 1];
                    __stcg(reinterpret_cast<float2*>(part2 + m * 64 + n), v);
                }
            }
        }
        signal_flag(&g_flagC[tileC * 32], tid);

        // ===== Phase D: newgate+blend for own 8 columns; needs flagC[tileC] >= 8(t+1) =====
        wait_flag(&g_flagC[tileC * 32], 8u * (t + 1));
        float hyv[2];
        {
            const float* p2 = g_part2[par] + (size_t)tileC * KSC * 4096;
            float* hb_n = g_hb[par ^ 1];
            #pragma unroll
            for (int it = 0; it < 2; it++) {
                int e = tid + it * NTH;
                int b = (it == 0) ? bown0 : bown1;
                int nn = nnC + (tid & 7);
                float hn = bcj;
                #pragma unroll
                for (int ks = 0; ks < KSC; ks++)
                    hn += __ldcg(p2 + ks * 4096 + b * 64 + nn);
                size_t bg = (size_t)b * G3;
                float n = tanhf(igt[bg + G2 + jown] + hn + ((it == 0) ? pn0 : pn1));
                float hold = sH[e];
                float hy = hold + sGi[e] * (n - hold);
                float hr_ = rndf(hy);
                sH[e] = hr_;
                __stcg(&hb_n[b * HH + jown], hr_);
                hyv[it] = hy;
            }
        }
        signal_flag(&g_flagD[(job >> 5) * 32], tid);
        // output stores AFTER the release — off the inter-CTA critical path
        #pragma unroll
        for (int it = 0; it < 2; it++) {
            int b = (it == 0) ? bown0 : bown1;
            out[((size_t)b * TT + t) * HH + jown] = hyv[it];
            if (want_hT && t == TT - 1)
                out[(size_t)BB * TT * HH + b * HH + jown] = hyv[it];
        }
    }
}

// ---------------- launch ----------------
extern "C" void kernel_launch(void* const* d_in, const int* in_sizes, int n_in,
                              void* d_out, int out_size)
{
    const float* x   = (const float*)d_in[0];
    const float* h0  = (const float*)d_in[1];
    const float* ctx = (const float*)d_in[2];
    const float* Wi  = (const float*)d_in[3];
    const float* bi  = (const float*)d_in[4];
    const float* Wh  = (const float*)d_in[5];
    const float* bh  = (const float*)d_in[6];
    const float* Wp  = (const float*)d_in[7];
    const float* bp  = (const float*)d_in[8];
    const float* Wc  = (const float*)d_in[9];
    const float* bc  = (const float*)d_in[10];
    float* out = (float*)d_out;

    float *p_ig, *p_p, *p_Wi, *p_Wp;
    cudaGetSymbolAddress((void**)&p_ig, g_ig);
    cudaGetSymbolAddress((void**)&p_p,  g_p);
    cudaGetSymbolAddress((void**)&p_Wi, g_Wi_t);
    cudaGetSymbolAddress((void**)&p_Wp, g_Wp_t);

    static const int SMEM_SCAN = (64 * WASTR + 64 * WCSTR + 64 * WASTR + 64 * 8 + 64 * 8) * 4;
    cudaFuncSetAttribute(scan_kernel, cudaFuncAttributeMaxDynamicSharedMemorySize, SMEM_SCAN);

    // prologue: round Wi, Wp to tf32 (Wh, Wc rounded during scan smem load)
    round_tf32_kernel<<<(G3 * DD + 255) / 256, 256>>>(Wi, p_Wi, G3 * DD);
    round_tf32_kernel<<<(G3 * HH + 255) / 256, 256>>>(Wp, p_Wp, G3 * HH);

    // ig_all[t][b][:] = x[b][t][:] @ Wi^T + bi   (time-major)
    mma_gemm_bias<<<dim3(G3 / 64, (TT * BB) / 64), NTH>>>(x, p_Wi, bi, p_ig, DD, G3, 1);

    // p[b][:] = ctx[b] @ Wp^T + bp
    mma_gemm_bias<<<dim3(G3 / 64, 1), NTH>>>(ctx, p_Wp, bp, p_p, HH, G3, 0);

    const int want_hT = (out_size >= (int)((size_t)BB * TT * HH + BB * HH)) ? 1 : 0;

    scan_kernel<<<NB, NTH, SMEM_SCAN>>>(h0, Wh, bh, Wc, bc, out, want_hT);
}